// round 11
// baseline (speedup 1.0000x reference)
#include <cuda_runtime.h>
#include <cstdint>

#define NBATCH 256
#define NN     64
#define DT     4096
#define THREADS 256
#define WAVE   64                      // batches per L2 wave

__device__ float e_scratch[NBATCH * NN];

#define XSTR 136                       // floats; 136 % 32 == 8 -> conflict-free B LDS
#define WSTR 68
#define SMF_W  0                       // 64*68      = 4352 floats
#define SMF_X0 (SMF_W + NN * WSTR)     // 64*136     = 8704 floats
#define SMF_X1 (SMF_X0 + NN * XSTR)
#define SMF_E  (SMF_X1 + NN * XSTR)
#define SMF_CF (SMF_E + NN)
#define SMEM_FLOATS (SMF_CF + 8)
#define SMEM_BYTES  (SMEM_FLOATS * 4)  // ~85.4 KB -> 2 CTAs/SM

__device__ __forceinline__ uint32_t f2tf32(float f) {
    uint32_t r;
    asm("cvt.rna.tf32.f32 %0, %1;" : "=r"(r) : "f"(f));
    return r;
}
__device__ __forceinline__ void mma_tf32(float& c0, float& c1, float& c2, float& c3,
                                         uint32_t a0, uint32_t a1, uint32_t a2, uint32_t a3,
                                         uint32_t b0, uint32_t b1) {
    asm volatile(
        "mma.sync.aligned.m16n8k8.row.col.f32.tf32.tf32.f32 "
        "{%0,%1,%2,%3}, {%4,%5,%6,%7}, {%8,%9}, {%0,%1,%2,%3};"
        : "+f"(c0), "+f"(c1), "+f"(c2), "+f"(c3)
        : "r"(a0), "r"(a1), "r"(a2), "r"(a3), "r"(b0), "r"(b1));
}
__device__ __forceinline__ void cp_async16(void* smem_dst, const void* gsrc) {
    unsigned sa = (unsigned)__cvta_generic_to_shared(smem_dst);
    asm volatile("cp.async.cg.shared.global [%0], [%1], 16;" :: "r"(sa), "l"(gsrc));
}
__device__ __forceinline__ void stg_cs_f2(float* p, float a, float b) {
    asm volatile("st.global.cs.v2.f32 [%0], {%1, %2};" :: "l"(p), "f"(a), "f"(b));
}

// ============================================================================
// Wave variance: grid 512 = (64 batches x 8 rowgroups), 1 row per warp.
// Reads the wave's 64 MB slab -> leaves it L2-resident.
// ============================================================================
__global__ void __launch_bounds__(THREADS, 4)
dga_var(const float* __restrict__ x, int bbase)
{
    const int b    = bbase + (blockIdx.x >> 3);
    const int r    = ((blockIdx.x & 7) << 3) + (threadIdx.x >> 5);
    const int lane = threadIdx.x & 31;
    const float4* row = (const float4*)(x + ((size_t)b * NN + r) * DT);

    float s = 0.f, ss = 0.f;
    #pragma unroll
    for (int k = 0; k < 32; ++k) {
        float4 v = row[lane + 32 * k];
        s  += (v.x + v.y) + (v.z + v.w);
        ss += v.x * v.x + v.y * v.y + v.z * v.z + v.w * v.w;
    }
    #pragma unroll
    for (int m = 16; m; m >>= 1) {
        s  += __shfl_xor_sync(0xffffffffu, s,  m);
        ss += __shfl_xor_sync(0xffffffffu, ss, m);
    }
    if (lane == 0) {
        float mean = s * (1.0f / DT);
        e_scratch[b * NN + r] = (ss - s * mean) * (1.0f / (DT - 1));
    }
}

// ============================================================================
// Wave GEMM: grid 512 = (64 batches x 8 t-slices of 512).
// Softmax computed in-CTA from e_scratch (slice 0 writes attn).
// X re-read hits L2; out written with .cs (evict-first) streaming stores.
// ============================================================================
__global__ void __launch_bounds__(THREADS, 2)
dga_gemm(const float* __restrict__ x,  const float* __restrict__ wq,
         const float* __restrict__ bq, const float* __restrict__ wk,
         const float* __restrict__ bk, float* __restrict__ out,
         float* __restrict__ attn, int bbase)
{
    extern __shared__ float smf[];
    float* w_sm = smf + SMF_W;
    float* e_sm = smf + SMF_E;
    float* coef = smf + SMF_CF;

    const int b    = bbase + (blockIdx.x >> 3);
    const int sl   = blockIdx.x & 7;          // t-slice (512 t)
    const int tid  = threadIdx.x;
    const int warp = tid >> 5;
    const int lane = tid & 31;
    const float* xb = x   + (size_t)b * NN * DT;
    float*       ob = out + (size_t)b * NN * DT;

    // ---- softmax weights from e (L2-hot) ----
    if (tid < NN) e_sm[tid] = e_scratch[b * NN + tid];
    if (tid == 0) {
        float A = 0.f, B = 0.f, C = 0.f, Dc = 0.f;
        #pragma unroll
        for (int h = 0; h < 16; ++h) {
            float q = wq[h], qb = bq[h], k = wk[h], kb = bk[h];
            A += q * k; B += q * kb; C += qb * k; Dc += qb * kb;
        }
        coef[0] = A; coef[1] = B; coef[2] = C; coef[3] = Dc;
    }
    __syncthreads();
    {
        const int i  = tid >> 2;
        const int jg = tid & 3;
        const float ei = e_sm[i];
        const float m1 = 0.25f * (coef[0] * ei + coef[2]);   // SCALE = 0.25
        const float m0 = 0.25f * (coef[1] * ei + coef[3]);
        float sv[16];
        float mx = -3.4e38f;
        #pragma unroll
        for (int t = 0; t < 16; ++t) {
            int j = jg * 16 + t;
            float s = fmaf(m1, e_sm[j], m0);
            if (j == i) s = -1000000000.0f;
            sv[t] = s;
            mx = fmaxf(mx, s);
        }
        #pragma unroll
        for (int m = 1; m < 4; m <<= 1)
            mx = fmaxf(mx, __shfl_xor_sync(0xffffffffu, mx, m));
        float sum = 0.f;
        #pragma unroll
        for (int t = 0; t < 16; ++t) { sv[t] = __expf(sv[t] - mx); sum += sv[t]; }
        #pragma unroll
        for (int m = 1; m < 4; m <<= 1)
            sum += __shfl_xor_sync(0xffffffffu, sum, m);
        float inv = 1.0f / sum;

        float* arow = attn + (((size_t)b * NN) + i) * NN;
        #pragma unroll
        for (int t = 0; t < 16; ++t) {
            float w = sv[t] * inv;
            w_sm[i * WSTR + jg * 16 + t] = w;
            if (sl == 0) arow[jg * 16 + t] = w;   // one slice writes attn
        }
    }
    __syncthreads();

    // ---- A-fragments (W as tf32) in registers ----
    const int mw  = (warp & 3) * 16;
    const int nco = (warp >> 2) * 64;
    const int g   = lane >> 2;
    const int tg  = lane & 3;

    uint32_t A[8][4];
    #pragma unroll
    for (int ks = 0; ks < 8; ++ks) {
        A[ks][0] = f2tf32(w_sm[(mw + g)     * WSTR + ks * 8 + tg]);
        A[ks][1] = f2tf32(w_sm[(mw + g + 8) * WSTR + ks * 8 + tg]);
        A[ks][2] = f2tf32(w_sm[(mw + g)     * WSTR + ks * 8 + tg + 4]);
        A[ks][3] = f2tf32(w_sm[(mw + g + 8) * WSTR + ks * 8 + tg + 4]);
    }

    // ---- 4 chunks of 128 t, double-buffered cp.async (L2 hits) ----
    float* xbuf0 = smf + SMF_X0;
    float* xbuf1 = smf + SMF_X1;
    const int tbase = sl * 512;

    #pragma unroll
    for (int s = 0; s < 8; ++s) {
        int u = tid + 256 * s;
        int j = u >> 5, q = u & 31;
        cp_async16(&xbuf0[j * XSTR + q * 4], xb + (size_t)j * DT + tbase + q * 4);
    }
    asm volatile("cp.async.commit_group;");

    #pragma unroll 1
    for (int c = 0; c < 4; ++c) {
        const int t0 = tbase + c * 128;
        float* xc = (c & 1) ? xbuf1 : xbuf0;

        if (c + 1 < 4) {
            float* xn = (c & 1) ? xbuf0 : xbuf1;
            const float* src = xb + t0 + 128;
            #pragma unroll
            for (int s = 0; s < 8; ++s) {
                int u = tid + 256 * s;
                int j = u >> 5, q = u & 31;
                cp_async16(&xn[j * XSTR + q * 4], src + (size_t)j * DT + q * 4);
            }
            asm volatile("cp.async.commit_group;");
            asm volatile("cp.async.wait_group 1;");
        } else {
            asm volatile("cp.async.wait_group 0;");
        }
        __syncthreads();

        float C[8][4];
        #pragma unroll
        for (int t = 0; t < 8; ++t)
            C[t][0] = C[t][1] = C[t][2] = C[t][3] = 0.f;

        #pragma unroll
        for (int ks = 0; ks < 8; ++ks) {
            const float* b0r = &xc[(ks * 8 + tg)     * XSTR + nco + g];
            const float* b1r = &xc[(ks * 8 + tg + 4) * XSTR + nco + g];
            #pragma unroll
            for (int t = 0; t < 8; ++t) {
                uint32_t b0 = f2tf32(b0r[t * 8]);     // single-phase LDS.32
                uint32_t b1 = f2tf32(b1r[t * 8]);
                mma_tf32(C[t][0], C[t][1], C[t][2], C[t][3],
                         A[ks][0], A[ks][1], A[ks][2], A[ks][3], b0, b1);
            }
        }

        // epilogue: exact fp32 residual from smem; streaming stores
        #pragma unroll
        for (int t = 0; t < 8; ++t) {
            int lcol = nco + t * 8 + 2 * tg;
            float2 r0 = *(const float2*)&xc[(mw + g)     * XSTR + lcol];
            float2 r1 = *(const float2*)&xc[(mw + g + 8) * XSTR + lcol];
            stg_cs_f2(ob + (size_t)(mw + g)     * DT + t0 + lcol,
                      C[t][0] + r0.x, C[t][1] + r0.y);
            stg_cs_f2(ob + (size_t)(mw + g + 8) * DT + t0 + lcol,
                      C[t][2] + r1.x, C[t][3] + r1.y);
        }
        __syncthreads();   // compute(c) done before restaging this buffer
    }
}

extern "C" void kernel_launch(void* const* d_in, const int* in_sizes, int n_in,
                              void* d_out, int out_size) {
    const float* x  = (const float*)d_in[0];
    const float* wq = (const float*)d_in[1];
    const float* bq = (const float*)d_in[2];
    const float* wk = (const float*)d_in[3];
    const float* bk = (const float*)d_in[4];
    float* out  = (float*)d_out;
    float* attn = out + (size_t)NBATCH * NN * DT;   // out tensor first, then attn

    cudaFuncSetAttribute(dga_gemm, cudaFuncAttributeMaxDynamicSharedMemorySize,
                         SMEM_BYTES);

    for (int w = 0; w < NBATCH / WAVE; ++w) {
        int bbase = w * WAVE;
        dga_var <<<WAVE * 8, THREADS>>>(x, bbase);
        dga_gemm<<<WAVE * 8, THREADS, SMEM_BYTES>>>(x, wq, bq, wk, bk,
                                                    out, attn, bbase);
    }
}